// round 15
// baseline (speedup 1.0000x reference)
#include <cuda_runtime.h>
#include <math.h>

// ---------------------------------------------------------------------------
// Problem constants (irreps 32x0e + 16x1o + 8x2e, edge sh 0e+1o+2e)
// ---------------------------------------------------------------------------
#define TM       64      // edges per CTA in tp_kernel
#define NTHREADS 256
#define WN       3456    // tp.weight_numel
#define NCHUNK   54      // 3456 / 64

// scratch (device globals — no allocation allowed)
__device__ float g_H[65536 * 64];     // per-edge hidden (E,64)
__device__ float g_agg[8192 * 120];   // scatter accumulator (N,120)
__device__ float g_w3j[363];          // packed Wigner-3j tables

// path tables: (i1,i2,i3) in e3nn order
__constant__ int   c_l1[11]    = {0,0,0,1,1,1,1,2,2,2,2};
__constant__ int   c_l2[11]    = {0,1,2,0,1,1,2,0,1,2,2};
__constant__ int   c_l3[11]    = {0,1,2,1,0,2,1,2,1,0,2};
__constant__ int   c_m1[11]    = {32,32,32,16,16,16,16, 8, 8, 8, 8};
__constant__ int   c_mO[11]    = {32,16, 8,16,32, 8,16, 8,16,32, 8};
__constant__ int   c_d1[11]    = {1,1,1,3,3,3,3,5,5,5,5};
__constant__ int   c_d2[11]    = {1,3,5,1,3,3,5,1,3,5,5};
__constant__ int   c_d3[11]    = {1,3,5,3,1,5,3,5,3,1,5};
__constant__ int   c_off1[11]  = {0,0,0,32,32,32,32,80,80,80,80};
__constant__ int   c_offO[11]  = {0,32,80,32,0,80,32,80,32,0,80};
__constant__ int   c_shoff[11] = {0,1,4,0,1,1,4,0,1,4,4};
__constant__ int   c_woff[11]  = {0,1024,1536,1792,2048,2560,2688,2944,3008,3136,3392};
__constant__ int   c_cgoff[11] = {0,1,10,35,44,53,98,143,168,213,238};
// COEF[i3] = sqrt((2*l+1)/fan): fan 56/72/64
__constant__ float c_coef[11]  = {
    0.13363062095621219f, 0.20412414523193154f, 0.27950849718747373f,
    0.20412414523193154f, 0.13363062095621219f, 0.27950849718747373f,
    0.20412414523193154f, 0.27950849718747373f, 0.20412414523193154f,
    0.13363062095621219f, 0.27950849718747373f };
// which path each 64-col chunk of W3 belongs to (all boundaries are x64)
__constant__ unsigned char c_chunkPath[NCHUNK] = {
    0,0,0,0,0,0,0,0,0,0,0,0,0,0,0,0,
    1,1,1,1,1,1,1,1,
    2,2,2,2,
    3,3,3,3,
    4,4,4,4,4,4,4,4,
    5,5,
    6,6,6,6,
    7,
    8,8,
    9,9,9,9,
    10 };

// ---------------------------------------------------------------------------
// f32x2 packed FMA helpers (FFMA2 — only reachable via PTX on sm_103a)
// ---------------------------------------------------------------------------
__device__ __forceinline__ unsigned long long pack2(float a, float b) {
    unsigned long long r;
    asm("mov.b64 %0, {%1,%2};" : "=l"(r) : "f"(a), "f"(b));
    return r;
}
#define FFMA2(d, a, b) \
    asm("fma.rn.f32x2 %0, %1, %2, %0;" : "+l"(d) : "l"(a), "l"(b))
#define UNPACK2(lo, hi, v) \
    asm("mov.b64 {%0,%1}, %2;" : "=f"(lo), "=f"(hi) : "l"(v))

// ---------------------------------------------------------------------------
// Wigner-3j init — mirrors the reference numpy code exactly (fp64)
// ---------------------------------------------------------------------------
__device__ double dfac(int n) {
    double r = 1.0;
    for (int i = 2; i <= n; ++i) r *= (double)i;
    return r;
}

__device__ double cgc(int j1, int m1, int j2, int m2, int j3, int m3) {
    if (m1 + m2 != m3) return 0.0;
    double pref = (2.0*j3+1.0) * dfac(j1+j2-j3) * dfac(j1-j2+j3) * dfac(-j1+j2+j3)
                  / dfac(j1+j2+j3+1);
    pref *= dfac(j1+m1)*dfac(j1-m1)*dfac(j2+m2)*dfac(j2-m2)*dfac(j3+m3)*dfac(j3-m3);
    int k0 = 0;
    if (j2-j3-m1 > k0) k0 = j2-j3-m1;
    if (j1-j3+m2 > k0) k0 = j1-j3+m2;
    int k1 = j1+j2-j3;
    if (j1-m1 < k1) k1 = j1-m1;
    if (j2+m2 < k1) k1 = j2+m2;
    double s = 0.0;
    for (int k = k0; k <= k1; ++k) {
        double t = dfac(k)*dfac(j1+j2-j3-k)*dfac(j1-m1-k)*dfac(j2+m2-k)
                   *dfac(j3-j2+m1+k)*dfac(j3-j1-m2+k);
        s += ((k & 1) ? -1.0 : 1.0) / t;
    }
    return sqrt(pref) * s;
}

__device__ void build_q(int l, double* qr, double* qi) {
    int d = 2*l + 1;
    for (int i = 0; i < d*d; ++i) { qr[i] = 0.0; qi[i] = 0.0; }
    const double s2 = 0.70710678118654752440;
    for (int m = -l; m < 0; ++m) {
        qr[(l+m)*d + (l-m)] = s2;    // q[l+m, l+|m|] = 1/sqrt(2)
        qi[(l+m)*d + (l+m)] = -s2;   // q[l+m, l-|m|] = -i/sqrt(2)
    }
    qr[l*d + l] = 1.0;
    for (int m = 1; m <= l; ++m) {
        double sgn = (m & 1) ? -1.0 : 1.0;
        qr[(l+m)*d + (l+m)] = sgn * s2;   // (-1)^m/sqrt(2)
        qi[(l+m)*d + (l-m)] = sgn * s2;   // i*(-1)^m/sqrt(2)
    }
    // multiply by (-i)^l
    if (l == 1) {
        for (int i = 0; i < d*d; ++i) { double a = qr[i], b = qi[i]; qr[i] = b; qi[i] = -a; }
    } else if (l == 2) {
        for (int i = 0; i < d*d; ++i) { qr[i] = -qr[i]; qi[i] = -qi[i]; }
    }
}

__global__ void init_w3j_kernel() {
    int p = threadIdx.x;
    if (p >= 11) return;
    int l1 = c_l1[p], l2 = c_l2[p], l3 = c_l3[p];
    int d1 = 2*l1+1, d2 = 2*l2+1, d3 = 2*l3+1;
    double q1r[25], q1i[25], q2r[25], q2i[25], q3r[25], q3i[25];
    build_q(l1, q1r, q1i);
    build_q(l2, q2r, q2i);
    build_q(l3, q3r, q3i);
    double C[125];
    for (int i = 0; i < d1*d2*d3; ++i) C[i] = 0.0;
    double inv = 1.0 / sqrt((double)(2*l3 + 1));
    for (int m1 = -l1; m1 <= l1; ++m1)
        for (int m2 = -l2; m2 <= l2; ++m2) {
            int m3 = m1 + m2;
            if (m3 >= -l3 && m3 <= l3)
                C[((l1+m1)*d2 + (l2+m2))*d3 + (l3+m3)] = cgc(l1,m1,l2,m2,l3,m3) * inv;
        }
    // einsum 'ij,kl,mn,ikn->jlm':
    //   Cr[j,l,m] = sum_{i,k,n} q1[i,j] * q2[k,l] * conj(q3)[m,n] * C[i,k,n]
    // NOTE: q1,q2 contracted over their ROW index; q3 over its COLUMN index
    // (output index m is q3's ROW). This asymmetry is load-bearing.
    double Crr[125], Cii[125];
    for (int j = 0; j < d1; ++j)
        for (int l = 0; l < d2; ++l)
            for (int m = 0; m < d3; ++m) {
                double sr = 0.0, si = 0.0;
                for (int i = 0; i < d1; ++i)
                    for (int k = 0; k < d2; ++k)
                        for (int n = 0; n < d3; ++n) {
                            double c = C[(i*d2 + k)*d3 + n];
                            if (c == 0.0) continue;
                            double ar = q1r[i*d1 + j], ai = q1i[i*d1 + j];
                            double br = q2r[k*d2 + l], bi = q2i[k*d2 + l];
                            double abr = ar*br - ai*bi;
                            double abi = ar*bi + ai*br;
                            double cr  =  q3r[m*d3 + n];   // conj(q3)[m,n]
                            double cim = -q3i[m*d3 + n];
                            sr += (abr*cr - abi*cim) * c;
                            si += (abr*cim + abi*cr) * c;
                        }
                Crr[(j*d2 + l)*d3 + m] = sr;
                Cii[(j*d2 + l)*d3 + m] = si;
            }
    int sz = d1*d2*d3;
    double nr = 0.0, ni = 0.0;
    for (int i = 0; i < sz; ++i) { nr += Crr[i]*Crr[i]; ni += Cii[i]*Cii[i]; }
    const double* S = (nr >= ni) ? Crr : Cii;
    double nn = sqrt((nr >= ni) ? nr : ni);
    for (int i = 0; i < sz; ++i)
        g_w3j[c_cgoff[p] + i] = (float)(S[i] / nn);
}

// ---------------------------------------------------------------------------
__global__ void zero_agg_kernel(int n) {
    int i = blockIdx.x * blockDim.x + threadIdx.x;
    if (i < n) g_agg[i] = 0.0f;
}

// ---------------------------------------------------------------------------
// radial MLP: (E,8) -> silu -> (E,64) -> silu -> g_H (E,64)
// 1024 threads = 16 edges x 64 neurons per block
// ---------------------------------------------------------------------------
__global__ __launch_bounds__(1024) void mlp_kernel(
    const float* __restrict__ radial,
    const float* __restrict__ W1, const float* __restrict__ b1,
    const float* __restrict__ W2, const float* __restrict__ b2,
    int E)
{
    __shared__ float rS[16][8];
    __shared__ float h1S[16][64];
    int tid = threadIdx.x;
    int e0 = blockIdx.x * 16;
    if (tid < 128) {
        int e = tid >> 3, j = tid & 7;
        int eg = e0 + e;
        rS[e][j] = (eg < E) ? radial[eg*8 + j] : 0.0f;
    }
    __syncthreads();
    int e = tid >> 6, o = tid & 63;
    float s = b1[o];
#pragma unroll
    for (int j = 0; j < 8; ++j) s += rS[e][j] * W1[j*64 + o];
    s = s / (1.0f + expf(-s));      // silu
    h1S[e][o] = s;
    __syncthreads();
    float s2 = b2[o];
#pragma unroll 8
    for (int j = 0; j < 64; ++j) s2 += h1S[e][j] * W2[j*64 + o];
    s2 = s2 / (1.0f + expf(-s2));
    int eg = e0 + e;
    if (eg < E) g_H[eg*64 + o] = s2;
}

// ---------------------------------------------------------------------------
// Fused tensor-product kernel: 64 edges per CTA.
// For each 64-col chunk of W3: smem GEMM (h block @ W3 chunk, FFMA2) -> wpS,
// then path-aware consumption against tmp[e,u,k] = sum_i x[e,u,i] B[e,i,k],
// B[e,i,k] = sum_j sh[e,j] C[i,j,k]. Messages atomically scattered to g_agg.
// ---------------------------------------------------------------------------
// smem float offsets
#define SM_HS    0            // [64k][68]   h block, k-major, padded
#define SM_W3    4352         // [64k][64]   W3 chunk
#define SM_WP    8448         // [64e][68]   wp tile (GEMM out + bias)
#define SM_B3    12800        // [64]        bias chunk
#define SM_X     12864        // [64e][120]  gathered node features
#define SM_SH    20544        // [64e][12]   edge sh (padded 9->12)
#define SM_ACC   21312        // [64e][120]  message accumulator
#define SM_TMP   28992        // [64e][164]  tmp (max mul1*d3 = 160)
#define SM_BB    39488        // [64e][28]   B (max d1*d3 = 25)
#define SM_CS    41280        // [128]       current CG table
#define SM_SRC   41408        // [64] int
#define SM_DST   41472        // [64] int
#define SM_FLOATS 41536
#define SMEM_BYTES (SM_FLOATS * 4)

__global__ __launch_bounds__(NTHREADS, 1) void tp_kernel(
    const float* __restrict__ nf,      // (N,120)
    const int*   __restrict__ ei,      // (2,E)
    const float* __restrict__ sh,      // (E,9)
    const float* __restrict__ W3g,     // (64,3456)
    const float* __restrict__ b3g,     // (3456)
    int N, int E)
{
    extern __shared__ float sm[];
    float* HsT  = sm + SM_HS;
    float* W3s  = sm + SM_W3;
    float* wpS  = sm + SM_WP;
    float* b3s  = sm + SM_B3;
    float* xS   = sm + SM_X;
    float* shS  = sm + SM_SH;
    float* accS = sm + SM_ACC;
    float* tmp  = sm + SM_TMP;
    float* Bs   = sm + SM_BB;
    float* Cs   = sm + SM_CS;
    int*   srcS = (int*)(sm + SM_SRC);
    int*   dstS = (int*)(sm + SM_DST);

    const int tid = threadIdx.x;
    const int e0  = blockIdx.x * TM;

    // ---- prologue ----
    for (int idx = tid; idx < TM; idx += NTHREADS) {
        int eg = e0 + idx;
        srcS[idx] = (eg < E) ? ei[eg] : 0;
        dstS[idx] = (eg < E) ? ei[E + eg] : 0;
    }
    for (int idx = tid; idx < TM * 64; idx += NTHREADS) {
        int e = idx >> 6, k = idx & 63;
        int eg = e0 + e;
        HsT[k*68 + e] = (eg < E) ? g_H[eg*64 + k] : 0.0f;
    }
    __syncthreads();
    for (int idx = tid; idx < TM * 120; idx += NTHREADS) {
        int e = idx / 120, f = idx - e*120;
        int eg = e0 + e;
        xS[idx]   = (eg < E) ? nf[srcS[e]*120 + f] : 0.0f;
        accS[idx] = 0.0f;
    }
    for (int idx = tid; idx < TM * 9; idx += NTHREADS) {
        int e = idx / 9, j = idx - e*9;
        int eg = e0 + e;
        shS[e*12 + j] = (eg < E) ? sh[eg*9 + j] : 0.0f;
    }
    __syncthreads();

    const int tx = tid & 15, ty = tid >> 4;   // 16x16 grid, 4 rows x 4 cols each
    int prevPath = -1;

    for (int ci = 0; ci < NCHUNK; ++ci) {
        const int p    = c_chunkPath[ci];
        const int mul1 = c_m1[p],  mulO = c_mO[p];
        const int d1   = c_d1[p],  d2   = c_d2[p],  d3 = c_d3[p];
        const int off1 = c_off1[p], offO = c_offO[p];
        const int shoff = c_shoff[p], woff = c_woff[p];
        const float coef = c_coef[p];

        if (p != prevPath) {
            __syncthreads();   // prior consumption done before tmp/Bs/Cs overwrite
            int csz = d1 * d2 * d3;
            for (int idx = tid; idx < csz; idx += NTHREADS)
                Cs[idx] = g_w3j[c_cgoff[p] + idx];
            __syncthreads();
            // B[e,i,k] = sum_j sh[e,j] C[i,j,k]
            int bitems = TM * d1 * d3;
            for (int idx = tid; idx < bitems; idx += NTHREADS) {
                int e = idx / (d1*d3);
                int r = idx - e*(d1*d3);
                int i = r / d3, k = r - i*d3;
                float s = 0.0f;
                for (int j = 0; j < d2; ++j)
                    s += shS[e*12 + shoff + j] * Cs[(i*d2 + j)*d3 + k];
                Bs[e*28 + i*d3 + k] = s;
            }
            __syncthreads();
            // tmp[e,u,k] = sum_i x[e,u,i] B[e,i,k]
            int titems = TM * mul1 * d3;
            for (int idx = tid; idx < titems; idx += NTHREADS) {
                int e = idx / (mul1*d3);
                int r = idx - e*(mul1*d3);
                int u = r / d3, k = r - u*d3;
                float s = 0.0f;
                const float* xp = &xS[e*120 + off1 + u*d1];
                const float* bp = &Bs[e*28 + k];
                for (int i = 0; i < d1; ++i) s += xp[i] * bp[i*d3];
                tmp[e*164 + u*d3 + k] = s;
            }
            prevPath = p;
            // tmp visibility is covered by the post-load sync below
        }

        const int colbase = ci * 64;
        // ---- load W3 chunk + bias ----
        for (int idx = tid; idx < 64*64; idx += NTHREADS) {
            int k = idx >> 6, col = idx & 63;
            W3s[idx] = W3g[k*WN + colbase + col];
        }
        if (tid < 64) b3s[tid] = b3g[colbase + tid];
        __syncthreads();   // W3s/tmp ready AND previous consumption done

        // ---- GEMM: wp[e,col] = sum_k h[e,k] * W3[k,col], packed f32x2 ----
        unsigned long long acc2[4][2];
#pragma unroll
        for (int i = 0; i < 4; ++i) { acc2[i][0] = 0ull; acc2[i][1] = 0ull; }
        const float* hb = &HsT[ty * 4];
        const float* wb = &W3s[tx * 4];
#pragma unroll 4
        for (int k = 0; k < 64; ++k) {
            float4 av = *(const float4*)(hb + k*68);
            float4 bv = *(const float4*)(wb + k*64);
            unsigned long long b01 = pack2(bv.x, bv.y);
            unsigned long long b23 = pack2(bv.z, bv.w);
            unsigned long long a;
            a = pack2(av.x, av.x); FFMA2(acc2[0][0], a, b01); FFMA2(acc2[0][1], a, b23);
            a = pack2(av.y, av.y); FFMA2(acc2[1][0], a, b01); FFMA2(acc2[1][1], a, b23);
            a = pack2(av.z, av.z); FFMA2(acc2[2][0], a, b01); FFMA2(acc2[2][1], a, b23);
            a = pack2(av.w, av.w); FFMA2(acc2[3][0], a, b01); FFMA2(acc2[3][1], a, b23);
        }
        {
            float bb0 = b3s[tx*4+0], bb1 = b3s[tx*4+1];
            float bb2 = b3s[tx*4+2], bb3 = b3s[tx*4+3];
#pragma unroll
            for (int i = 0; i < 4; ++i) {
                float l0, h0, l1, h1;
                UNPACK2(l0, h0, acc2[i][0]);
                UNPACK2(l1, h1, acc2[i][1]);
                float4 o = make_float4(l0 + bb0, h0 + bb1, l1 + bb2, h1 + bb3);
                *(float4*)&wpS[(ty*4 + i)*68 + tx*4] = o;
            }
        }
        __syncthreads();   // wpS ready

        // ---- consumption: acc[e,offO + w*d3 + k] += coef * sum_u wp*tmp ----
        const int u0 = (colbase - woff) / mulO;
        const int nu = 64 / mulO;
        const int items = TM * mulO;
        for (int it = tid; it < items; it += NTHREADS) {
            int e = it / mulO, w = it - e*mulO;
            const float* wpp = &wpS[e*68 + w];
            const float* tpp = &tmp[e*164 + u0*d3];
            float* ap = &accS[e*120 + offO + w*d3];
            if (d3 == 1) {
                float s = 0.0f;
                for (int uu = 0; uu < nu; ++uu) s += wpp[uu*mulO] * tpp[uu];
                ap[0] += coef * s;
            } else if (d3 == 3) {
                float s0 = 0, s1 = 0, s2 = 0;
                for (int uu = 0; uu < nu; ++uu) {
                    float wv = wpp[uu*mulO];
                    const float* t = &tpp[uu*3];
                    s0 += wv*t[0]; s1 += wv*t[1]; s2 += wv*t[2];
                }
                ap[0] += coef*s0; ap[1] += coef*s1; ap[2] += coef*s2;
            } else { // d3 == 5
                float s0 = 0, s1 = 0, s2 = 0, s3 = 0, s4 = 0;
                for (int uu = 0; uu < nu; ++uu) {
                    float wv = wpp[uu*mulO];
                    const float* t = &tpp[uu*5];
                    s0 += wv*t[0]; s1 += wv*t[1]; s2 += wv*t[2];
                    s3 += wv*t[3]; s4 += wv*t[4];
                }
                ap[0] += coef*s0; ap[1] += coef*s1; ap[2] += coef*s2;
                ap[3] += coef*s3; ap[4] += coef*s4;
            }
        }
    }
    __syncthreads();

    // ---- scatter messages into g_agg ----
    for (int idx = tid; idx < TM * 120; idx += NTHREADS) {
        int e = idx / 120, f = idx - e*120;
        if (e0 + e < E)
            atomicAdd(&g_agg[dstS[e]*120 + f], accS[idx]);
    }
}

// ---------------------------------------------------------------------------
// output: block-diagonal linear * 1/sqrt(mul) + residual
// ---------------------------------------------------------------------------
__global__ void out_kernel(
    const float* __restrict__ nf,
    const float* __restrict__ Ws0,
    const float* __restrict__ Ws1,
    const float* __restrict__ Ws2,
    float* __restrict__ out, int N)
{
    int idx = blockIdx.x * blockDim.x + threadIdx.x;
    if (idx >= N * 120) return;
    int n = idx / 120, f = idx - n * 120;
    int off, mul, d;
    const float* W;
    float inv;
    if (f < 32)      { off = 0;  mul = 32; d = 1; W = Ws0; inv = 0.17677669529663687f; }
    else if (f < 80) { off = 32; mul = 16; d = 3; W = Ws1; inv = 0.25f; }
    else             { off = 80; mul = 8;  d = 5; W = Ws2; inv = 0.35355339059327373f; }
    int r = f - off;
    int v = r / d, k = r - v * d;
    const float* a = &g_agg[n * 120 + off + k];
    float s = 0.0f;
    for (int u = 0; u < mul; ++u)
        s += a[u * d] * W[u * mul + v];
    out[idx] = s * inv + nf[idx];
}

// ---------------------------------------------------------------------------
extern "C" void kernel_launch(void* const* d_in, const int* in_sizes, int n_in,
                              void* d_out, int out_size) {
    const float* node_features = (const float*)d_in[0];
    const int*   edge_index    = (const int*)  d_in[1];
    const float* edge_sh       = (const float*)d_in[2];
    const float* edge_radial   = (const float*)d_in[3];
    const float* W1  = (const float*)d_in[4];
    const float* b1  = (const float*)d_in[5];
    const float* W2  = (const float*)d_in[6];
    const float* b2  = (const float*)d_in[7];
    const float* W3  = (const float*)d_in[8];
    const float* b3  = (const float*)d_in[9];
    const float* Ws0 = (const float*)d_in[10];
    const float* Ws1 = (const float*)d_in[11];
    const float* Ws2 = (const float*)d_in[12];
    float* out = (float*)d_out;

    const int N = in_sizes[0] / 120;
    const int E = in_sizes[2] / 9;

    cudaFuncSetAttribute(tp_kernel,
        cudaFuncAttributeMaxDynamicSharedMemorySize, SMEM_BYTES);

    init_w3j_kernel<<<1, 32>>>();
    zero_agg_kernel<<<(N * 120 + 255) / 256, 256>>>(N * 120);
    mlp_kernel<<<(E + 15) / 16, 1024>>>(edge_radial, W1, b1, W2, b2, E);
    tp_kernel<<<(E + TM - 1) / TM, NTHREADS, SMEM_BYTES>>>(
        node_features, edge_index, edge_sh, W3, b3, N, E);
    out_kernel<<<(N * 120 + 255) / 256, 256>>>(node_features, Ws0, Ws1, Ws2, out, N);
}

// round 16
// speedup vs baseline: 2.5072x; 2.5072x over previous
#include <cuda_runtime.h>
#include <math.h>

// ---------------------------------------------------------------------------
// Problem constants (irreps 32x0e + 16x1o + 8x2e, edge sh 0e+1o+2e)
// ---------------------------------------------------------------------------
#define TM       64      // edges per CTA in tp_kernel
#define NTHREADS 512
#define WN       3456    // tp.weight_numel
#define NCHUNK   54      // 3456 / 64

// scratch (device globals — no allocation allowed)
__device__ float g_H[65536 * 64];     // per-edge hidden (E,64)
__device__ float g_agg[8192 * 120];   // scatter accumulator (N,120)
__device__ float g_w3j[363];          // packed Wigner-3j tables

// path tables: (i1,i2,i3) in e3nn order
__constant__ int   c_l1[11]    = {0,0,0,1,1,1,1,2,2,2,2};
__constant__ int   c_l2[11]    = {0,1,2,0,1,1,2,0,1,2,2};
__constant__ int   c_l3[11]    = {0,1,2,1,0,2,1,2,1,0,2};
__constant__ int   c_m1[11]    = {32,32,32,16,16,16,16, 8, 8, 8, 8};
__constant__ int   c_mO[11]    = {32,16, 8,16,32, 8,16, 8,16,32, 8};
__constant__ int   c_d1[11]    = {1,1,1,3,3,3,3,5,5,5,5};
__constant__ int   c_d2[11]    = {1,3,5,1,3,3,5,1,3,5,5};
__constant__ int   c_d3[11]    = {1,3,5,3,1,5,3,5,3,1,5};
__constant__ int   c_off1[11]  = {0,0,0,32,32,32,32,80,80,80,80};
__constant__ int   c_offO[11]  = {0,32,80,32,0,80,32,80,32,0,80};
__constant__ int   c_shoff[11] = {0,1,4,0,1,1,4,0,1,4,4};
__constant__ int   c_woff[11]  = {0,1024,1536,1792,2048,2560,2688,2944,3008,3136,3392};
__constant__ int   c_cgoff[11] = {0,1,10,35,44,53,98,143,168,213,238};
// COEF[i3] = sqrt((2*l+1)/fan): fan 56/72/64
__constant__ float c_coef[11]  = {
    0.13363062095621219f, 0.20412414523193154f, 0.27950849718747373f,
    0.20412414523193154f, 0.13363062095621219f, 0.27950849718747373f,
    0.20412414523193154f, 0.27950849718747373f, 0.20412414523193154f,
    0.13363062095621219f, 0.27950849718747373f };
// which path each 64-col chunk of W3 belongs to (all boundaries are x64)
__constant__ unsigned char c_chunkPath[NCHUNK] = {
    0,0,0,0,0,0,0,0,0,0,0,0,0,0,0,0,
    1,1,1,1,1,1,1,1,
    2,2,2,2,
    3,3,3,3,
    4,4,4,4,4,4,4,4,
    5,5,
    6,6,6,6,
    7,
    8,8,
    9,9,9,9,
    10 };

// ---------------------------------------------------------------------------
// f32x2 packed FMA helpers (FFMA2 — only reachable via PTX on sm_103a)
// ---------------------------------------------------------------------------
__device__ __forceinline__ unsigned long long pack2(float a, float b) {
    unsigned long long r;
    asm("mov.b64 %0, {%1,%2};" : "=l"(r) : "f"(a), "f"(b));
    return r;
}
#define FFMA2(d, a, b) \
    asm("fma.rn.f32x2 %0, %1, %2, %0;" : "+l"(d) : "l"(a), "l"(b))
#define UNPACK2(lo, hi, v) \
    asm("mov.b64 {%0,%1}, %2;" : "=f"(lo), "=f"(hi) : "l"(v))

// ---------------------------------------------------------------------------
// Wigner-3j init — same math as the verified R15 version, but parallel:
// one warp per path, q/C tables in shared, outputs spread across lanes.
// ---------------------------------------------------------------------------
__device__ double dfac(int n) {
    double r = 1.0;
    for (int i = 2; i <= n; ++i) r *= (double)i;
    return r;
}

__device__ double cgc(int j1, int m1, int j2, int m2, int j3, int m3) {
    if (m1 + m2 != m3) return 0.0;
    double pref = (2.0*j3+1.0) * dfac(j1+j2-j3) * dfac(j1-j2+j3) * dfac(-j1+j2+j3)
                  / dfac(j1+j2+j3+1);
    pref *= dfac(j1+m1)*dfac(j1-m1)*dfac(j2+m2)*dfac(j2-m2)*dfac(j3+m3)*dfac(j3-m3);
    int k0 = 0;
    if (j2-j3-m1 > k0) k0 = j2-j3-m1;
    if (j1-j3+m2 > k0) k0 = j1-j3+m2;
    int k1 = j1+j2-j3;
    if (j1-m1 < k1) k1 = j1-m1;
    if (j2+m2 < k1) k1 = j2+m2;
    double s = 0.0;
    for (int k = k0; k <= k1; ++k) {
        double t = dfac(k)*dfac(j1+j2-j3-k)*dfac(j1-m1-k)*dfac(j2+m2-k)
                   *dfac(j3-j2+m1+k)*dfac(j3-j1-m2+k);
        s += ((k & 1) ? -1.0 : 1.0) / t;
    }
    return sqrt(pref) * s;
}

__device__ void build_q(int l, double* qr, double* qi) {
    int d = 2*l + 1;
    for (int i = 0; i < d*d; ++i) { qr[i] = 0.0; qi[i] = 0.0; }
    const double s2 = 0.70710678118654752440;
    for (int m = -l; m < 0; ++m) {
        qr[(l+m)*d + (l-m)] = s2;    // q[l+m, l+|m|] = 1/sqrt(2)
        qi[(l+m)*d + (l+m)] = -s2;   // q[l+m, l-|m|] = -i/sqrt(2)
    }
    qr[l*d + l] = 1.0;
    for (int m = 1; m <= l; ++m) {
        double sgn = (m & 1) ? -1.0 : 1.0;
        qr[(l+m)*d + (l+m)] = sgn * s2;   // (-1)^m/sqrt(2)
        qi[(l+m)*d + (l-m)] = sgn * s2;   // i*(-1)^m/sqrt(2)
    }
    // multiply by (-i)^l
    if (l == 1) {
        for (int i = 0; i < d*d; ++i) { double a = qr[i], b = qi[i]; qr[i] = b; qi[i] = -a; }
    } else if (l == 2) {
        for (int i = 0; i < d*d; ++i) { qr[i] = -qr[i]; qi[i] = -qi[i]; }
    }
}

__global__ __launch_bounds__(352) void init_w3j_kernel() {
    __shared__ double Csh[11][125];
    __shared__ double qs[11][6][25];  // [path][q1r,q1i,q2r,q2i,q3r,q3i][..]
    int p = threadIdx.x >> 5;
    int lane = threadIdx.x & 31;
    if (p >= 11) return;
    int l1 = c_l1[p], l2 = c_l2[p], l3 = c_l3[p];
    int d1 = 2*l1+1, d2 = 2*l2+1, d3 = 2*l3+1;

    for (int i = lane; i < 125; i += 32) Csh[p][i] = 0.0;
    if (lane == 0) {
        build_q(l1, qs[p][0], qs[p][1]);
        build_q(l2, qs[p][2], qs[p][3]);
        build_q(l3, qs[p][4], qs[p][5]);
    }
    __syncwarp();

    // C[i,k,n] = cgc(l1,m1,l2,m2,l3,m3)/sqrt(2*l3+1), one (m1,m2) per lane
    double inv = 1.0 / sqrt((double)(2*l3 + 1));
    if (lane < d1*d2) {
        int i = lane / d2, k = lane - i*d2;
        int m1 = i - l1, m2 = k - l2, m3 = m1 + m2;
        if (m3 >= -l3 && m3 <= l3)
            Csh[p][(i*d2 + k)*d3 + (l3 + m3)] = cgc(l1,m1,l2,m2,l3,m3) * inv;
    }
    __syncwarp();

    // einsum 'ij,kl,mn,ikn->jlm':
    //   Cr[j,l,m] = sum_{i,k,n} q1[i,j] * q2[k,l] * conj(q3)[m,n] * C[i,k,n]
    // (q1,q2 contracted over ROW; q3 over COLUMN — asymmetry is load-bearing)
    int sz = d1*d2*d3;
    double outR[4], outI[4];
    double nr = 0.0, ni = 0.0;
#pragma unroll
    for (int t = 0; t < 4; ++t) {
        outR[t] = 0.0; outI[t] = 0.0;
        int o = lane + t*32;
        if (o < sz) {
            int j = o / (d2*d3);
            int rem = o - j*(d2*d3);
            int l = rem / d3;
            int m = rem - l*d3;
            double sr = 0.0, si = 0.0;
            for (int i = 0; i < d1; ++i)
                for (int k = 0; k < d2; ++k) {
                    double ar = qs[p][0][i*d1+j], ai = qs[p][1][i*d1+j];
                    double br = qs[p][2][k*d2+l], bi = qs[p][3][k*d2+l];
                    double abr = ar*br - ai*bi;
                    double abi = ar*bi + ai*br;
                    for (int n = 0; n < d3; ++n) {
                        double c = Csh[p][(i*d2 + k)*d3 + n];
                        if (c == 0.0) continue;
                        double cr  =  qs[p][4][m*d3+n];   // conj(q3)[m,n]
                        double cim = -qs[p][5][m*d3+n];
                        sr += (abr*cr - abi*cim) * c;
                        si += (abr*cim + abi*cr) * c;
                    }
                }
            outR[t] = sr; outI[t] = si;
            nr += sr*sr; ni += si*si;
        }
    }
    // warp-reduce Frobenius norms
    for (int off = 16; off; off >>= 1) {
        nr += __shfl_xor_sync(0xffffffffu, nr, off);
        ni += __shfl_xor_sync(0xffffffffu, ni, off);
    }
    bool useR = (nr >= ni);
    double nn = sqrt(useR ? nr : ni);
#pragma unroll
    for (int t = 0; t < 4; ++t) {
        int o = lane + t*32;
        if (o < sz)
            g_w3j[c_cgoff[p] + o] = (float)((useR ? outR[t] : outI[t]) / nn);
    }
}

// ---------------------------------------------------------------------------
__global__ void zero_agg_kernel(int n) {
    int i = blockIdx.x * blockDim.x + threadIdx.x;
    if (i < n) g_agg[i] = 0.0f;
}

// ---------------------------------------------------------------------------
// radial MLP: (E,8) -> silu -> (E,64) -> silu -> g_H (E,64)
// ---------------------------------------------------------------------------
__global__ __launch_bounds__(1024) void mlp_kernel(
    const float* __restrict__ radial,
    const float* __restrict__ W1, const float* __restrict__ b1,
    const float* __restrict__ W2, const float* __restrict__ b2,
    int E)
{
    __shared__ float rS[16][8];
    __shared__ float h1S[16][64];
    int tid = threadIdx.x;
    int e0 = blockIdx.x * 16;
    if (tid < 128) {
        int e = tid >> 3, j = tid & 7;
        int eg = e0 + e;
        rS[e][j] = (eg < E) ? radial[eg*8 + j] : 0.0f;
    }
    __syncthreads();
    int e = tid >> 6, o = tid & 63;
    float s = b1[o];
#pragma unroll
    for (int j = 0; j < 8; ++j) s += rS[e][j] * W1[j*64 + o];
    s = s / (1.0f + expf(-s));      // silu
    h1S[e][o] = s;
    __syncthreads();
    float s2 = b2[o];
#pragma unroll 8
    for (int j = 0; j < 64; ++j) s2 += h1S[e][j] * W2[j*64 + o];
    s2 = s2 / (1.0f + expf(-s2));
    int eg = e0 + e;
    if (eg < E) g_H[eg*64 + o] = s2;
}

// ---------------------------------------------------------------------------
// Fused tensor-product kernel: 64 edges per CTA, 512 threads.
// Per 64-col chunk of W3: smem GEMM (FFMA2, 2x4 tile) -> wpS, then path-aware
// consumption vs tmp[e,u,k] = sum_i x[e,u,i] B[e,i,k]. Scatter to g_agg.
// ---------------------------------------------------------------------------
// smem float offsets
#define SM_HS    0            // [64k][68]   h block, k-major, padded
#define SM_W3    4352         // [64k][64]   W3 chunk
#define SM_WP    8448         // [64e][68]   wp tile (GEMM out + bias)
#define SM_B3    12800        // [64]        bias chunk
#define SM_X     12864        // [64e][120]  gathered node features
#define SM_SH    20544        // [64e][12]   edge sh (padded 9->12)
#define SM_ACC   21312        // [64e][120]  message accumulator
#define SM_TMP   28992        // [64e][164]  tmp (max mul1*d3 = 160)
#define SM_BB    39488        // [64e][28]   B (max d1*d3 = 25)
#define SM_CS    41280        // [128]       current CG table
#define SM_SRC   41408        // [64] int
#define SM_DST   41472        // [64] int
#define SM_FLOATS 41536
#define SMEM_BYTES (SM_FLOATS * 4)

__global__ __launch_bounds__(NTHREADS, 1) void tp_kernel(
    const float* __restrict__ nf,      // (N,120)
    const int*   __restrict__ ei,      // (2,E)
    const float* __restrict__ sh,      // (E,9)
    const float* __restrict__ W3g,     // (64,3456)
    const float* __restrict__ b3g,     // (3456)
    int N, int E)
{
    extern __shared__ float sm[];
    float* HsT  = sm + SM_HS;
    float* W3s  = sm + SM_W3;
    float* wpS  = sm + SM_WP;
    float* b3s  = sm + SM_B3;
    float* xS   = sm + SM_X;
    float* shS  = sm + SM_SH;
    float* accS = sm + SM_ACC;
    float* tmp  = sm + SM_TMP;
    float* Bs   = sm + SM_BB;
    float* Cs   = sm + SM_CS;
    int*   srcS = (int*)(sm + SM_SRC);
    int*   dstS = (int*)(sm + SM_DST);

    const int tid = threadIdx.x;
    const int e0  = blockIdx.x * TM;

    // ---- prologue ----
    for (int idx = tid; idx < TM; idx += NTHREADS) {
        int eg = e0 + idx;
        srcS[idx] = (eg < E) ? ei[eg] : 0;
        dstS[idx] = (eg < E) ? ei[E + eg] : 0;
    }
    // h block transpose: float4 loads, scalar transposed stores
    for (int idx = tid; idx < TM * 16; idx += NTHREADS) {
        int e = idx >> 4, kg = idx & 15;
        int eg = e0 + e;
        float4 v = make_float4(0.f,0.f,0.f,0.f);
        if (eg < E) v = *(const float4*)&g_H[eg*64 + kg*4];
        HsT[(kg*4+0)*68 + e] = v.x;
        HsT[(kg*4+1)*68 + e] = v.y;
        HsT[(kg*4+2)*68 + e] = v.z;
        HsT[(kg*4+3)*68 + e] = v.w;
    }
    __syncthreads();
    // x gather (float4) + acc zero
    for (int idx = tid; idx < TM * 30; idx += NTHREADS) {
        int e = idx / 30, fg = idx - e*30;
        int eg = e0 + e;
        float4 v = make_float4(0.f,0.f,0.f,0.f);
        if (eg < E) v = *(const float4*)&nf[srcS[e]*120 + fg*4];
        *(float4*)&xS[e*120 + fg*4]   = v;
        *(float4*)&accS[e*120 + fg*4] = make_float4(0.f,0.f,0.f,0.f);
    }
    for (int idx = tid; idx < TM * 9; idx += NTHREADS) {
        int e = idx / 9, j = idx - e*9;
        int eg = e0 + e;
        shS[e*12 + j] = (eg < E) ? sh[eg*9 + j] : 0.0f;
    }
    __syncthreads();

    const int tx = tid & 15, ty = tid >> 4;   // 16 col-groups x 32 row-groups
    int prevPath = -1;

    for (int ci = 0; ci < NCHUNK; ++ci) {
        const int p    = c_chunkPath[ci];
        const int mul1 = c_m1[p],  mulO = c_mO[p];
        const int d1   = c_d1[p],  d2   = c_d2[p],  d3 = c_d3[p];
        const int off1 = c_off1[p], offO = c_offO[p];
        const int shoff = c_shoff[p], woff = c_woff[p];
        const float coef = c_coef[p];

        if (p != prevPath) {
            __syncthreads();   // prior consumption done before tmp/Bs/Cs overwrite
            int csz = d1 * d2 * d3;
            for (int idx = tid; idx < csz; idx += NTHREADS)
                Cs[idx] = g_w3j[c_cgoff[p] + idx];
            __syncthreads();
            // B[e,i,k] = sum_j sh[e,j] C[i,j,k]
            int bitems = TM * d1 * d3;
            for (int idx = tid; idx < bitems; idx += NTHREADS) {
                int e = idx / (d1*d3);
                int r = idx - e*(d1*d3);
                int i = r / d3, k = r - i*d3;
                float s = 0.0f;
                for (int j = 0; j < d2; ++j)
                    s += shS[e*12 + shoff + j] * Cs[(i*d2 + j)*d3 + k];
                Bs[e*28 + i*d3 + k] = s;
            }
            __syncthreads();
            // tmp[e,u,k] = sum_i x[e,u,i] B[e,i,k]
            int titems = TM * mul1 * d3;
            for (int idx = tid; idx < titems; idx += NTHREADS) {
                int e = idx / (mul1*d3);
                int r = idx - e*(mul1*d3);
                int u = r / d3, k = r - u*d3;
                float s = 0.0f;
                const float* xp = &xS[e*120 + off1 + u*d1];
                const float* bp = &Bs[e*28 + k];
                for (int i = 0; i < d1; ++i) s += xp[i] * bp[i*d3];
                tmp[e*164 + u*d3 + k] = s;
            }
            prevPath = p;
            // tmp visibility is covered by the post-load sync below
        }

        const int colbase = ci * 64;
        // ---- load W3 chunk (float4) + bias ----
        for (int idx = tid; idx < 1024; idx += NTHREADS) {
            int k = idx >> 4, cg = idx & 15;
            *(float4*)&W3s[k*64 + cg*4] = *(const float4*)&W3g[k*WN + colbase + cg*4];
        }
        if (tid < 64) b3s[tid] = b3g[colbase + tid];
        __syncthreads();   // W3s/tmp ready AND previous consumption done

        // ---- GEMM: wp[e,col] = sum_k h[e,k]*W3[k,col]; 2 rows x 4 cols ----
        // B operand comes straight from a 16B LDS as two packed f32x2 (no MOVs)
        unsigned long long acc00 = 0ull, acc01 = 0ull, acc10 = 0ull, acc11 = 0ull;
        const float* hb = &HsT[ty * 2];
        const float* wb = &W3s[tx * 4];
#pragma unroll 8
        for (int k = 0; k < 64; ++k) {
            float2 av = *(const float2*)(hb + k*68);
            ulonglong2 bv = *(const ulonglong2*)(wb + k*64);
            unsigned long long a0 = pack2(av.x, av.x);
            unsigned long long a1 = pack2(av.y, av.y);
            FFMA2(acc00, a0, bv.x); FFMA2(acc01, a0, bv.y);
            FFMA2(acc10, a1, bv.x); FFMA2(acc11, a1, bv.y);
        }
        {
            float bb0 = b3s[tx*4+0], bb1 = b3s[tx*4+1];
            float bb2 = b3s[tx*4+2], bb3 = b3s[tx*4+3];
            float l0, h0, l1, h1;
            UNPACK2(l0, h0, acc00);
            UNPACK2(l1, h1, acc01);
            *(float4*)&wpS[(ty*2+0)*68 + tx*4] =
                make_float4(l0 + bb0, h0 + bb1, l1 + bb2, h1 + bb3);
            UNPACK2(l0, h0, acc10);
            UNPACK2(l1, h1, acc11);
            *(float4*)&wpS[(ty*2+1)*68 + tx*4] =
                make_float4(l0 + bb0, h0 + bb1, l1 + bb2, h1 + bb3);
        }
        __syncthreads();   // wpS ready

        // ---- consumption: acc[e,offO + w*d3 + k] += coef * sum_u wp*tmp ----
        const int u0 = (colbase - woff) / mulO;
        const int nu = 64 / mulO;
        const int items = TM * mulO;
        for (int it = tid; it < items; it += NTHREADS) {
            int e = it / mulO, w = it - e*mulO;
            const float* wpp = &wpS[e*68 + w];
            const float* tpp = &tmp[e*164 + u0*d3];
            float* ap = &accS[e*120 + offO + w*d3];
            if (d3 == 1) {
                float s = 0.0f;
                for (int uu = 0; uu < nu; ++uu) s += wpp[uu*mulO] * tpp[uu];
                ap[0] += coef * s;
            } else if (d3 == 3) {
                float s0 = 0, s1 = 0, s2 = 0;
                for (int uu = 0; uu < nu; ++uu) {
                    float wv = wpp[uu*mulO];
                    const float* t = &tpp[uu*3];
                    s0 += wv*t[0]; s1 += wv*t[1]; s2 += wv*t[2];
                }
                ap[0] += coef*s0; ap[1] += coef*s1; ap[2] += coef*s2;
            } else { // d3 == 5
                float s0 = 0, s1 = 0, s2 = 0, s3 = 0, s4 = 0;
                for (int uu = 0; uu < nu; ++uu) {
                    float wv = wpp[uu*mulO];
                    const float* t = &tpp[uu*5];
                    s0 += wv*t[0]; s1 += wv*t[1]; s2 += wv*t[2];
                    s3 += wv*t[3]; s4 += wv*t[4];
                }
                ap[0] += coef*s0; ap[1] += coef*s1; ap[2] += coef*s2;
                ap[3] += coef*s3; ap[4] += coef*s4;
            }
        }
    }
    __syncthreads();

    // ---- scatter messages into g_agg ----
    for (int idx = tid; idx < TM * 120; idx += NTHREADS) {
        int e = idx / 120, f = idx - e*120;
        if (e0 + e < E)
            atomicAdd(&g_agg[dstS[e]*120 + f], accS[idx]);
    }
}

// ---------------------------------------------------------------------------
// output: block-diagonal linear * 1/sqrt(mul) + residual
// ---------------------------------------------------------------------------
__global__ void out_kernel(
    const float* __restrict__ nf,
    const float* __restrict__ Ws0,
    const float* __restrict__ Ws1,
    const float* __restrict__ Ws2,
    float* __restrict__ out, int N)
{
    int idx = blockIdx.x * blockDim.x + threadIdx.x;
    if (idx >= N * 120) return;
    int n = idx / 120, f = idx - n * 120;
    int off, mul, d;
    const float* W;
    float inv;
    if (f < 32)      { off = 0;  mul = 32; d = 1; W = Ws0; inv = 0.17677669529663687f; }
    else if (f < 80) { off = 32; mul = 16; d = 3; W = Ws1; inv = 0.25f; }
    else             { off = 80; mul = 8;  d = 5; W = Ws2; inv = 0.35355339059327373f; }
    int r = f - off;
    int v = r / d, k = r - v * d;
    const float* a = &g_agg[n * 120 + off + k];
    float s = 0.0f;
    for (int u = 0; u < mul; ++u)
        s += a[u * d] * W[u * mul + v];
    out[idx] = s * inv + nf[idx];
}

// ---------------------------------------------------------------------------
extern "C" void kernel_launch(void* const* d_in, const int* in_sizes, int n_in,
                              void* d_out, int out_size) {
    const float* node_features = (const float*)d_in[0];
    const int*   edge_index    = (const int*)  d_in[1];
    const float* edge_sh       = (const float*)d_in[2];
    const float* edge_radial   = (const float*)d_in[3];
    const float* W1  = (const float*)d_in[4];
    const float* b1  = (const float*)d_in[5];
    const float* W2  = (const float*)d_in[6];
    const float* b2  = (const float*)d_in[7];
    const float* W3  = (const float*)d_in[8];
    const float* b3  = (const float*)d_in[9];
    const float* Ws0 = (const float*)d_in[10];
    const float* Ws1 = (const float*)d_in[11];
    const float* Ws2 = (const float*)d_in[12];
    float* out = (float*)d_out;

    const int N = in_sizes[0] / 120;
    const int E = in_sizes[2] / 9;

    cudaFuncSetAttribute(tp_kernel,
        cudaFuncAttributeMaxDynamicSharedMemorySize, SMEM_BYTES);

    init_w3j_kernel<<<1, 352>>>();
    zero_agg_kernel<<<(N * 120 + 255) / 256, 256>>>(N * 120);
    mlp_kernel<<<(E + 15) / 16, 1024>>>(edge_radial, W1, b1, W2, b2, E);
    tp_kernel<<<(E + TM - 1) / TM, NTHREADS, SMEM_BYTES>>>(
        node_features, edge_index, edge_sh, W3, b3, N, E);
    out_kernel<<<(N * 120 + 255) / 256, 256>>>(node_features, Ws0, Ws1, Ws2, out, N);
}

// round 17
// speedup vs baseline: 5.4826x; 2.1868x over previous
#include <cuda_runtime.h>
#include <math.h>

// ---------------------------------------------------------------------------
// Problem constants (irreps 32x0e + 16x1o + 8x2e, edge sh 0e+1o+2e)
// ---------------------------------------------------------------------------
#define TM       64      // edges per CTA in tp_kernel
#define NTHREADS 512
#define WN       3456    // tp.weight_numel
#define NSTEP    28      // schedule: 128-col steps (64-col at path boundaries)

// scratch (device globals — no allocation allowed)
__device__ float g_H[65536 * 64];     // per-edge hidden (E,64)
__device__ float g_agg[8192 * 120];   // scatter accumulator (N,120)
__device__ float g_w3j[363];          // packed Wigner-3j tables

// path tables: (i1,i2,i3) in e3nn order
__constant__ int   c_l1[11]    = {0,0,0,1,1,1,1,2,2,2,2};
__constant__ int   c_l2[11]    = {0,1,2,0,1,1,2,0,1,2,2};
__constant__ int   c_l3[11]    = {0,1,2,1,0,2,1,2,1,0,2};
__constant__ int   c_m1[11]    = {32,32,32,16,16,16,16, 8, 8, 8, 8};
__constant__ int   c_mO[11]    = {32,16, 8,16,32, 8,16, 8,16,32, 8};
__constant__ int   c_d1[11]    = {1,1,1,3,3,3,3,5,5,5,5};
__constant__ int   c_d2[11]    = {1,3,5,1,3,3,5,1,3,5,5};
__constant__ int   c_d3[11]    = {1,3,5,3,1,5,3,5,3,1,5};
__constant__ int   c_off1[11]  = {0,0,0,32,32,32,32,80,80,80,80};
__constant__ int   c_offO[11]  = {0,32,80,32,0,80,32,80,32,0,80};
__constant__ int   c_shoff[11] = {0,1,4,0,1,1,4,0,1,4,4};
__constant__ int   c_woff[11]  = {0,1024,1536,1792,2048,2560,2688,2944,3008,3136,3392};
__constant__ int   c_cgoff[11] = {0,1,10,35,44,53,98,143,168,213,238};
// COEF[i3] = sqrt((2*l+1)/fan): fan 56/72/64
__constant__ float c_coef[11]  = {
    0.13363062095621219f, 0.20412414523193154f, 0.27950849718747373f,
    0.20412414523193154f, 0.13363062095621219f, 0.27950849718747373f,
    0.20412414523193154f, 0.27950849718747373f, 0.20412414523193154f,
    0.13363062095621219f, 0.27950849718747373f };
// GEMM schedule: column base, width, path per step (all within one path)
__constant__ short c_stepCb[NSTEP] = {
    0,128,256,384,512,640,768,896,
    1024,1152,1280,1408,
    1536,1664,
    1792,1920,
    2048,2176,2304,2432,
    2560,
    2688,2816,
    2944,
    3008,
    3136,3264,
    3392 };
__constant__ short c_stepN[NSTEP] = {
    128,128,128,128,128,128,128,128,
    128,128,128,128,
    128,128,
    128,128,
    128,128,128,128,
    128,
    128,128,
    64,
    128,
    128,128,
    64 };
__constant__ unsigned char c_stepPath[NSTEP] = {
    0,0,0,0,0,0,0,0,
    1,1,1,1,
    2,2,
    3,3,
    4,4,4,4,
    5,
    6,6,
    7,
    8,
    9,9,
    10 };

// ---------------------------------------------------------------------------
// f32x2 packed FMA helpers (FFMA2 — only reachable via PTX on sm_103a)
// ---------------------------------------------------------------------------
__device__ __forceinline__ unsigned long long pack2(float a, float b) {
    unsigned long long r;
    asm("mov.b64 %0, {%1,%2};" : "=l"(r) : "f"(a), "f"(b));
    return r;
}
#define FFMA2(d, a, b) \
    asm("fma.rn.f32x2 %0, %1, %2, %0;" : "+l"(d) : "l"(a), "l"(b))
#define UNPACK2(lo, hi, v) \
    asm("mov.b64 {%0,%1}, %2;" : "=f"(lo), "=f"(hi) : "l"(v))

// ---------------------------------------------------------------------------
// Wigner-3j init — verified math, parallel: one warp per path.
// ---------------------------------------------------------------------------
__device__ double dfac(int n) {
    double r = 1.0;
    for (int i = 2; i <= n; ++i) r *= (double)i;
    return r;
}

__device__ double cgc(int j1, int m1, int j2, int m2, int j3, int m3) {
    if (m1 + m2 != m3) return 0.0;
    double pref = (2.0*j3+1.0) * dfac(j1+j2-j3) * dfac(j1-j2+j3) * dfac(-j1+j2+j3)
                  / dfac(j1+j2+j3+1);
    pref *= dfac(j1+m1)*dfac(j1-m1)*dfac(j2+m2)*dfac(j2-m2)*dfac(j3+m3)*dfac(j3-m3);
    int k0 = 0;
    if (j2-j3-m1 > k0) k0 = j2-j3-m1;
    if (j1-j3+m2 > k0) k0 = j1-j3+m2;
    int k1 = j1+j2-j3;
    if (j1-m1 < k1) k1 = j1-m1;
    if (j2+m2 < k1) k1 = j2+m2;
    double s = 0.0;
    for (int k = k0; k <= k1; ++k) {
        double t = dfac(k)*dfac(j1+j2-j3-k)*dfac(j1-m1-k)*dfac(j2+m2-k)
                   *dfac(j3-j2+m1+k)*dfac(j3-j1-m2+k);
        s += ((k & 1) ? -1.0 : 1.0) / t;
    }
    return sqrt(pref) * s;
}

__device__ void build_q(int l, double* qr, double* qi) {
    int d = 2*l + 1;
    for (int i = 0; i < d*d; ++i) { qr[i] = 0.0; qi[i] = 0.0; }
    const double s2 = 0.70710678118654752440;
    for (int m = -l; m < 0; ++m) {
        qr[(l+m)*d + (l-m)] = s2;    // q[l+m, l+|m|] = 1/sqrt(2)
        qi[(l+m)*d + (l+m)] = -s2;   // q[l+m, l-|m|] = -i/sqrt(2)
    }
    qr[l*d + l] = 1.0;
    for (int m = 1; m <= l; ++m) {
        double sgn = (m & 1) ? -1.0 : 1.0;
        qr[(l+m)*d + (l+m)] = sgn * s2;   // (-1)^m/sqrt(2)
        qi[(l+m)*d + (l-m)] = sgn * s2;   // i*(-1)^m/sqrt(2)
    }
    // multiply by (-i)^l
    if (l == 1) {
        for (int i = 0; i < d*d; ++i) { double a = qr[i], b = qi[i]; qr[i] = b; qi[i] = -a; }
    } else if (l == 2) {
        for (int i = 0; i < d*d; ++i) { qr[i] = -qr[i]; qi[i] = -qi[i]; }
    }
}

__global__ __launch_bounds__(352) void init_w3j_kernel() {
    __shared__ double Csh[11][125];
    __shared__ double qs[11][6][25];  // [path][q1r,q1i,q2r,q2i,q3r,q3i][..]
    int p = threadIdx.x >> 5;
    int lane = threadIdx.x & 31;
    if (p >= 11) return;
    int l1 = c_l1[p], l2 = c_l2[p], l3 = c_l3[p];
    int d1 = 2*l1+1, d2 = 2*l2+1, d3 = 2*l3+1;

    for (int i = lane; i < 125; i += 32) Csh[p][i] = 0.0;
    if (lane == 0) {
        build_q(l1, qs[p][0], qs[p][1]);
        build_q(l2, qs[p][2], qs[p][3]);
        build_q(l3, qs[p][4], qs[p][5]);
    }
    __syncwarp();

    double inv = 1.0 / sqrt((double)(2*l3 + 1));
    if (lane < d1*d2) {
        int i = lane / d2, k = lane - i*d2;
        int m1 = i - l1, m2 = k - l2, m3 = m1 + m2;
        if (m3 >= -l3 && m3 <= l3)
            Csh[p][(i*d2 + k)*d3 + (l3 + m3)] = cgc(l1,m1,l2,m2,l3,m3) * inv;
    }
    __syncwarp();

    // einsum 'ij,kl,mn,ikn->jlm':
    //   Cr[j,l,m] = sum_{i,k,n} q1[i,j] * q2[k,l] * conj(q3)[m,n] * C[i,k,n]
    int sz = d1*d2*d3;
    double outR[4], outI[4];
    double nr = 0.0, ni = 0.0;
#pragma unroll
    for (int t = 0; t < 4; ++t) {
        outR[t] = 0.0; outI[t] = 0.0;
        int o = lane + t*32;
        if (o < sz) {
            int j = o / (d2*d3);
            int rem = o - j*(d2*d3);
            int l = rem / d3;
            int m = rem - l*d3;
            double sr = 0.0, si = 0.0;
            for (int i = 0; i < d1; ++i)
                for (int k = 0; k < d2; ++k) {
                    double ar = qs[p][0][i*d1+j], ai = qs[p][1][i*d1+j];
                    double br = qs[p][2][k*d2+l], bi = qs[p][3][k*d2+l];
                    double abr = ar*br - ai*bi;
                    double abi = ar*bi + ai*br;
                    for (int n = 0; n < d3; ++n) {
                        double c = Csh[p][(i*d2 + k)*d3 + n];
                        if (c == 0.0) continue;
                        double cr  =  qs[p][4][m*d3+n];   // conj(q3)[m,n]
                        double cim = -qs[p][5][m*d3+n];
                        sr += (abr*cr - abi*cim) * c;
                        si += (abr*cim + abi*cr) * c;
                    }
                }
            outR[t] = sr; outI[t] = si;
            nr += sr*sr; ni += si*si;
        }
    }
    for (int off = 16; off; off >>= 1) {
        nr += __shfl_xor_sync(0xffffffffu, nr, off);
        ni += __shfl_xor_sync(0xffffffffu, ni, off);
    }
    bool useR = (nr >= ni);
    double nn = sqrt(useR ? nr : ni);
#pragma unroll
    for (int t = 0; t < 4; ++t) {
        int o = lane + t*32;
        if (o < sz)
            g_w3j[c_cgoff[p] + o] = (float)((useR ? outR[t] : outI[t]) / nn);
    }
}

// ---------------------------------------------------------------------------
__global__ void zero_agg_kernel(int n) {
    int i = blockIdx.x * blockDim.x + threadIdx.x;
    if (i < n) g_agg[i] = 0.0f;
}

// ---------------------------------------------------------------------------
// radial MLP: (E,8) -> silu -> (E,64) -> silu -> g_H (E,64)
// ---------------------------------------------------------------------------
__global__ __launch_bounds__(1024) void mlp_kernel(
    const float* __restrict__ radial,
    const float* __restrict__ W1, const float* __restrict__ b1,
    const float* __restrict__ W2, const float* __restrict__ b2,
    int E)
{
    __shared__ float rS[16][8];
    __shared__ float h1S[16][64];
    int tid = threadIdx.x;
    int e0 = blockIdx.x * 16;
    if (tid < 128) {
        int e = tid >> 3, j = tid & 7;
        int eg = e0 + e;
        rS[e][j] = (eg < E) ? radial[eg*8 + j] : 0.0f;
    }
    __syncthreads();
    int e = tid >> 6, o = tid & 63;
    float s = b1[o];
#pragma unroll
    for (int j = 0; j < 8; ++j) s += rS[e][j] * W1[j*64 + o];
    s = s / (1.0f + expf(-s));      // silu
    h1S[e][o] = s;
    __syncthreads();
    float s2 = b2[o];
#pragma unroll 8
    for (int j = 0; j < 64; ++j) s2 += h1S[e][j] * W2[j*64 + o];
    s2 = s2 / (1.0f + expf(-s2));
    int eg = e0 + e;
    if (eg < E) g_H[eg*64 + o] = s2;
}

// ---------------------------------------------------------------------------
// Fused tensor-product kernel: 64 edges/CTA, 512 threads, 128-col GEMM steps.
// GEMM tile 4x4 per thread: A float4 (broadcast), B ulonglong2 -> FFMA2.
// ---------------------------------------------------------------------------
// smem float offsets
#define SM_HS    0            // [64k][68]    h block, k-major, padded
#define SM_W3    4352         // [64k][128]   W3 step (up to 128 cols)
#define SM_WP    12544        // [64e][132]   wp tile (GEMM out + bias)
#define SM_B3    20992        // [128]        bias step
#define SM_X     21120        // [64e][120]   gathered node features
#define SM_SH    28800        // [64e][12]    edge sh (padded 9->12)
#define SM_ACC   29568        // [64e][120]   message accumulator
#define SM_TMP   37248        // [64e][164]   tmp (max mul1*d3 = 160)
#define SM_BB    47744        // [64e][28]    B (max d1*d3 = 25)
#define SM_CS    49536        // [128]        current CG table
#define SM_SRC   49664        // [64] int
#define SM_DST   49728        // [64] int
#define SM_FLOATS 49792
#define SMEM_BYTES (SM_FLOATS * 4)   // 199168 B

__global__ __launch_bounds__(NTHREADS, 1) void tp_kernel(
    const float* __restrict__ nf,      // (N,120)
    const int*   __restrict__ ei,      // (2,E)
    const float* __restrict__ sh,      // (E,9)
    const float* __restrict__ W3g,     // (64,3456)
    const float* __restrict__ b3g,     // (3456)
    int N, int E)
{
    extern __shared__ float sm[];
    float* HsT  = sm + SM_HS;
    float* W3s  = sm + SM_W3;
    float* wpS  = sm + SM_WP;
    float* b3s  = sm + SM_B3;
    float* xS   = sm + SM_X;
    float* shS  = sm + SM_SH;
    float* accS = sm + SM_ACC;
    float* tmp  = sm + SM_TMP;
    float* Bs   = sm + SM_BB;
    float* Cs   = sm + SM_CS;
    int*   srcS = (int*)(sm + SM_SRC);
    int*   dstS = (int*)(sm + SM_DST);

    const int tid = threadIdx.x;
    const int e0  = blockIdx.x * TM;

    // ---- prologue ----
    for (int idx = tid; idx < TM; idx += NTHREADS) {
        int eg = e0 + idx;
        srcS[idx] = (eg < E) ? ei[eg] : 0;
        dstS[idx] = (eg < E) ? ei[E + eg] : 0;
    }
    // h block transpose: float4 loads, scalar transposed stores
    for (int idx = tid; idx < TM * 16; idx += NTHREADS) {
        int e = idx >> 4, kg = idx & 15;
        int eg = e0 + e;
        float4 v = make_float4(0.f,0.f,0.f,0.f);
        if (eg < E) v = *(const float4*)&g_H[eg*64 + kg*4];
        HsT[(kg*4+0)*68 + e] = v.x;
        HsT[(kg*4+1)*68 + e] = v.y;
        HsT[(kg*4+2)*68 + e] = v.z;
        HsT[(kg*4+3)*68 + e] = v.w;
    }
    __syncthreads();
    // x gather (float4) + acc zero
    for (int idx = tid; idx < TM * 30; idx += NTHREADS) {
        int e = idx / 30, fg = idx - e*30;
        int eg = e0 + e;
        float4 v = make_float4(0.f,0.f,0.f,0.f);
        if (eg < E) v = *(const float4*)&nf[srcS[e]*120 + fg*4];
        *(float4*)&xS[e*120 + fg*4]   = v;
        *(float4*)&accS[e*120 + fg*4] = make_float4(0.f,0.f,0.f,0.f);
    }
    for (int idx = tid; idx < TM * 9; idx += NTHREADS) {
        int e = idx / 9, j = idx - e*9;
        int eg = e0 + e;
        shS[e*12 + j] = (eg < E) ? sh[eg*9 + j] : 0.0f;
    }
    __syncthreads();

    const int tx = tid & 31, ty = tid >> 5;   // 32 col-groups x 16 row-groups
    int prevPath = -1;

    for (int si = 0; si < NSTEP; ++si) {
        const int p     = c_stepPath[si];
        const int ncols = c_stepN[si];
        const int colbase = c_stepCb[si];
        const int mul1 = c_m1[p],  mulO = c_mO[p];
        const int d1   = c_d1[p],  d2   = c_d2[p],  d3 = c_d3[p];
        const int off1 = c_off1[p], offO = c_offO[p];
        const int shoff = c_shoff[p], woff = c_woff[p];
        const float coef = c_coef[p];

        if (p != prevPath) {
            __syncthreads();   // prior consumption done before tmp/Bs/Cs overwrite
            int csz = d1 * d2 * d3;
            for (int idx = tid; idx < csz; idx += NTHREADS)
                Cs[idx] = g_w3j[c_cgoff[p] + idx];
            __syncthreads();
            // B[e,i,k] = sum_j sh[e,j] C[i,j,k]
            int bitems = TM * d1 * d3;
            for (int idx = tid; idx < bitems; idx += NTHREADS) {
                int e = idx / (d1*d3);
                int r = idx - e*(d1*d3);
                int i = r / d3, k = r - i*d3;
                float s = 0.0f;
                for (int j = 0; j < d2; ++j)
                    s += shS[e*12 + shoff + j] * Cs[(i*d2 + j)*d3 + k];
                Bs[e*28 + i*d3 + k] = s;
            }
            __syncthreads();
            // tmp[e,u,k] = sum_i x[e,u,i] B[e,i,k]
            int titems = TM * mul1 * d3;
            for (int idx = tid; idx < titems; idx += NTHREADS) {
                int e = idx / (mul1*d3);
                int r = idx - e*(mul1*d3);
                int u = r / d3, k = r - u*d3;
                float s = 0.0f;
                const float* xp = &xS[e*120 + off1 + u*d1];
                const float* bp = &Bs[e*28 + k];
                for (int i = 0; i < d1; ++i) s += xp[i] * bp[i*d3];
                tmp[e*164 + u*d3 + k] = s;
            }
            prevPath = p;
            // tmp visibility covered by the post-load sync below
        }

        // ---- load W3 step (float4) + bias ----
        if (ncols == 128) {
            for (int idx = tid; idx < 64*32; idx += NTHREADS) {
                int k = idx >> 5, cg = idx & 31;
                *(float4*)&W3s[k*128 + cg*4] =
                    *(const float4*)&W3g[k*WN + colbase + cg*4];
            }
        } else {
            for (int idx = tid; idx < 64*16; idx += NTHREADS) {
                int k = idx >> 4, cg = idx & 15;
                *(float4*)&W3s[k*128 + cg*4] =
                    *(const float4*)&W3g[k*WN + colbase + cg*4];
            }
        }
        if (tid < ncols) b3s[tid] = b3g[colbase + tid];
        __syncthreads();   // W3s/tmp ready AND previous consumption done

        // ---- GEMM: wp[e,col] = sum_k h[e,k]*W3[k,col]; 4 rows x 4 cols ----
        if (tx * 4 < ncols) {
            unsigned long long a00=0ull,a01=0ull,a10=0ull,a11=0ull;
            unsigned long long a20=0ull,a21=0ull,a30=0ull,a31=0ull;
            const float* hb = &HsT[ty * 4];
            const float* wb = &W3s[tx * 4];
#pragma unroll 8
            for (int k = 0; k < 64; ++k) {
                float4 av = *(const float4*)(hb + k*68);        // rows (broadcast in warp)
                ulonglong2 bv = *(const ulonglong2*)(wb + k*128); // 4 cols, pre-packed
                unsigned long long s;
                s = pack2(av.x, av.x); FFMA2(a00, s, bv.x); FFMA2(a01, s, bv.y);
                s = pack2(av.y, av.y); FFMA2(a10, s, bv.x); FFMA2(a11, s, bv.y);
                s = pack2(av.z, av.z); FFMA2(a20, s, bv.x); FFMA2(a21, s, bv.y);
                s = pack2(av.w, av.w); FFMA2(a30, s, bv.x); FFMA2(a31, s, bv.y);
            }
            float bb0 = b3s[tx*4+0], bb1 = b3s[tx*4+1];
            float bb2 = b3s[tx*4+2], bb3 = b3s[tx*4+3];
            float l0, h0, l1, h1;
            UNPACK2(l0, h0, a00); UNPACK2(l1, h1, a01);
            *(float4*)&wpS[(ty*4+0)*132 + tx*4] = make_float4(l0+bb0, h0+bb1, l1+bb2, h1+bb3);
            UNPACK2(l0, h0, a10); UNPACK2(l1, h1, a11);
            *(float4*)&wpS[(ty*4+1)*132 + tx*4] = make_float4(l0+bb0, h0+bb1, l1+bb2, h1+bb3);
            UNPACK2(l0, h0, a20); UNPACK2(l1, h1, a21);
            *(float4*)&wpS[(ty*4+2)*132 + tx*4] = make_float4(l0+bb0, h0+bb1, l1+bb2, h1+bb3);
            UNPACK2(l0, h0, a30); UNPACK2(l1, h1, a31);
            *(float4*)&wpS[(ty*4+3)*132 + tx*4] = make_float4(l0+bb0, h0+bb1, l1+bb2, h1+bb3);
        }
        __syncthreads();   // wpS ready

        // ---- consumption: acc[e,offO + w*d3 + k] += coef * sum_u wp*tmp ----
        const int u0 = (colbase - woff) / mulO;
        const int nu = ncols / mulO;
        const int items = TM * mulO;
        for (int it = tid; it < items; it += NTHREADS) {
            int e = it / mulO, w = it - e*mulO;
            const float* wpp = &wpS[e*132 + w];
            const float* tpp = &tmp[e*164 + u0*d3];
            float* ap = &accS[e*120 + offO + w*d3];
            if (d3 == 1) {
                float s = 0.0f;
                for (int uu = 0; uu < nu; ++uu) s += wpp[uu*mulO] * tpp[uu];
                ap[0] += coef * s;
            } else if (d3 == 3) {
                float s0 = 0, s1 = 0, s2 = 0;
                for (int uu = 0; uu < nu; ++uu) {
                    float wv = wpp[uu*mulO];
                    const float* t = &tpp[uu*3];
                    s0 += wv*t[0]; s1 += wv*t[1]; s2 += wv*t[2];
                }
                ap[0] += coef*s0; ap[1] += coef*s1; ap[2] += coef*s2;
            } else { // d3 == 5
                float s0 = 0, s1 = 0, s2 = 0, s3 = 0, s4 = 0;
                for (int uu = 0; uu < nu; ++uu) {
                    float wv = wpp[uu*mulO];
                    const float* t = &tpp[uu*5];
                    s0 += wv*t[0]; s1 += wv*t[1]; s2 += wv*t[2];
                    s3 += wv*t[3]; s4 += wv*t[4];
                }
                ap[0] += coef*s0; ap[1] += coef*s1; ap[2] += coef*s2;
                ap[3] += coef*s3; ap[4] += coef*s4;
            }
        }
    }
    __syncthreads();

    // ---- scatter messages into g_agg ----
    for (int idx = tid; idx < TM * 120; idx += NTHREADS) {
        int e = idx / 120, f = idx - e*120;
        if (e0 + e < E)
            atomicAdd(&g_agg[dstS[e]*120 + f], accS[idx]);
    }
}

// ---------------------------------------------------------------------------
// output: block-diagonal linear * 1/sqrt(mul) + residual
// ---------------------------------------------------------------------------
__global__ void out_kernel(
    const float* __restrict__ nf,
    const float* __restrict__ Ws0,
    const float* __restrict__ Ws1,
    const float* __restrict__ Ws2,
    float* __restrict__ out, int N)
{
    int idx = blockIdx.x * blockDim.x + threadIdx.x;
    if (idx >= N * 120) return;
    int n = idx / 120, f = idx - n * 120;
    int off, mul, d;
    const float* W;
    float inv;
    if (f < 32)      { off = 0;  mul = 32; d = 1; W = Ws0; inv = 0.17677669529663687f; }
    else if (f < 80) { off = 32; mul = 16; d = 3; W = Ws1; inv = 0.25f; }
    else             { off = 80; mul = 8;  d = 5; W = Ws2; inv = 0.35355339059327373f; }
    int r = f - off;
    int v = r / d, k = r - v * d;
    const float* a = &g_agg[n * 120 + off + k];
    float s = 0.0f;
    for (int u = 0; u < mul; ++u)
        s += a[u * d] * W[u * mul + v];
    out[idx] = s * inv + nf[idx];
}

// ---------------------------------------------------------------------------
extern "C" void kernel_launch(void* const* d_in, const int* in_sizes, int n_in,
                              void* d_out, int out_size) {
    const float* node_features = (const float*)d_in[0];
    const int*   edge_index    = (const int*)  d_in[1];
    const float* edge_sh       = (const float*)d_in[2];
    const float* edge_radial   = (const float*)d_in[3];
    const float* W1  = (const float*)d_in[4];
    const float* b1  = (const float*)d_in[5];
    const float* W2  = (const float*)d_in[6];
    const float* b2  = (const float*)d_in[7];
    const float* W3  = (const float*)d_in[8];
    const float* b3  = (const float*)d_in[9];
    const float* Ws0 = (const float*)d_in[10];
    const float* Ws1 = (const float*)d_in[11];
    const float* Ws2 = (const float*)d_in[12];
    float* out = (float*)d_out;

    const int N = in_sizes[0] / 120;
    const int E = in_sizes[2] / 9;

    cudaFuncSetAttribute(tp_kernel,
        cudaFuncAttributeMaxDynamicSharedMemorySize, SMEM_BYTES);

    init_w3j_kernel<<<1, 352>>>();
    zero_agg_kernel<<<(N * 120 + 255) / 256, 256>>>(N * 120);
    mlp_kernel<<<(E + 15) / 16, 1024>>>(edge_radial, W1, b1, W2, b2, E);
    tp_kernel<<<(E + TM - 1) / TM, NTHREADS, SMEM_BYTES>>>(
        node_features, edge_index, edge_sh, W3, b3, N, E);
    out_kernel<<<(N * 120 + 255) / 256, 256>>>(node_features, Ws0, Ws1, Ws2, out, N);
}